// round 4
// baseline (speedup 1.0000x reference)
#include <cuda_runtime.h>
#include <math.h>

#define A_N    76725
#define NCLS   80
#define NB     8
#define NTASK  (NB*NCLS)
#define KPRE   256
#define MDPC   100
#define MAXD   100
#define CCAP   3072          // per-task pushed-candidate capacity
#define BUFN   1024
#define NBIN   4096
#define PUSH_T 2.0f          // logit push threshold (count(x>2) >> 256 per task)

// ---------------- scratch ----------------
__device__ unsigned long long g_cand[(size_t)NTASK * CCAP];   // ~15.7MB
__device__ int    g_cnt[NTASK];
__device__ float  g_cls_scores[NTASK * MDPC];
__device__ float4 g_cls_boxes[NTASK * MDPC];

__device__ __forceinline__ unsigned fkey32(float x) {
    unsigned b = __float_as_uint(x);
    return (b & 0x80000000u) ? ~b : (b | 0x80000000u);
}

// inclusive suffix totals over 256 thread-chunks of BPT bins; returns grand total
template <int BPT>
__device__ __forceinline__ unsigned suffix_total(const unsigned* hist, unsigned* csum, int tid) {
    unsigned s = 0;
    const int base = tid * BPT;
#pragma unroll
    for (int r = 0; r < BPT; ++r) s += hist[base + r];
    csum[tid] = s;
    __syncthreads();
    for (int off = 1; off < 256; off <<= 1) {
        unsigned add = (tid + off < 256) ? csum[tid + off] : 0u;
        __syncthreads();
        csum[tid] += add;
        __syncthreads();
    }
    return csum[0];
}

// descending crossing: ctrl[0]=bin, ctrl[1]=count strictly above bin
template <int BPT>
__device__ __forceinline__ void crossing(const unsigned* hist, const unsigned* csum, int* ctrl,
                                         unsigned target, int tid) {
    unsigned run = (tid + 1 < 256) ? csum[tid + 1] : 0u;
    const int base = tid * BPT;
    for (int i = base + BPT - 1; i >= base; --i) {
        unsigned h = hist[i];
        run += h;
        if (run >= target && run - h < target) { ctrl[0] = i; ctrl[1] = (int)(run - h); }
    }
    __syncthreads();
}

// =====================================================================
__global__ void k_zero() {
    int i = blockIdx.x * 256 + threadIdx.x;
    if (i < NTASK) g_cnt[i] = 0;
}

// =====================================================================
// Kernel 1: stream predictions, push high-logit candidates per (b,c)
// =====================================================================
__global__ void __launch_bounds__(256) k_decode(const float* __restrict__ pred) {
    const int nT = 600;
    const int b  = blockIdx.x / nT;
    const int t  = blockIdx.x % nT;
    const int a0 = t << 7;
    const int na = min(128, A_N - a0);
    const float4* src = (const float4*)(pred + ((size_t)b * A_N + a0) * 84);
    const int tot = na * 21;

    for (int i = threadIdx.x; i < tot; i += 256) {
        float4 v = src[i];
        int la   = i / 21;
        int col0 = (i - la * 21) * 4;
        int a    = a0 + la;
        float xs[4] = { v.x, v.y, v.z, v.w };
#pragma unroll
        for (int j = 0; j < 4; ++j) {
            float x = xs[j];
            int col = col0 + j;
            if (col >= 4 && x > PUSH_T) {
                int c = col - 4;
                float s = 1.0f / (1.0f + expf(-x));
                int task = b * NCLS + c;
                int idx = atomicAdd(&g_cnt[task], 1);
                if (idx < CCAP) {
                    unsigned key = __float_as_uint(s) | 0x80000000u;
                    g_cand[(size_t)task * CCAP + idx] =
                        ((unsigned long long)key << 32) | (unsigned)(~(unsigned)a);
                }
            }
        }
    }
}

// =====================================================================
// Kernel 2: per (b,c) exact top-256 + greedy NMS + per-class top-100
// =====================================================================
__global__ void __launch_bounds__(256) k_select(const float* __restrict__ pred,
                                                const float* __restrict__ anchors) {
    extern __shared__ unsigned char sm[];
    unsigned long long* CAND = (unsigned long long*)sm;            // 24576B
    unsigned*           hist = (unsigned*)(sm + 24576);            // 16384B
    unsigned long long* BUF  = (unsigned long long*)(sm + 40960);  // 8192B
    unsigned*           csum = (unsigned*)(sm + 49152);            // 1028B
    int*                ctrl = (int*)(sm + 50184);                 // 32B

    const int tid  = threadIdx.x;
    const int task = blockIdx.x;
    const int b    = task / NCLS;
    const int c    = task % NCLS;

    const int n = g_cnt[task];
    const bool fast = (n >= KPRE && n <= CCAP);

    for (int i = tid; i < NBIN; i += 256) hist[i] = 0;
    if (tid < 8) ctrl[tid] = 0;
    __syncthreads();

    if (fast) {
        // ---- load candidates, two-level select among n (~1.7k) entries ----
        for (int i = tid; i < n; i += 256) CAND[i] = g_cand[(size_t)task * CCAP + i];
        __syncthreads();
        for (int i = tid; i < n; i += 256)
            atomicAdd(&hist[(unsigned)(CAND[i] >> 52)], 1u);
        __syncthreads();
        (void)suffix_total<16>(hist, csum, tid);
        crossing<16>(hist, csum, ctrl, KPRE, tid);
        const unsigned B1 = (unsigned)ctrl[0];
        const unsigned C1 = (unsigned)ctrl[1];
        __syncthreads();

        for (int i = tid; i < NBIN; i += 256) hist[i] = 0;
        __syncthreads();
        for (int i = tid; i < n; i += 256) {
            unsigned long long e = CAND[i];
            if ((unsigned)(e >> 52) == B1) atomicAdd(&hist[(unsigned)(e >> 40) & 0xFFFu], 1u);
        }
        __syncthreads();
        (void)suffix_total<16>(hist, csum, tid);
        crossing<16>(hist, csum, ctrl, KPRE - C1, tid);
        const unsigned B2 = (unsigned)ctrl[0];
        if (tid == 0) ctrl[2] = 0;
        __syncthreads();

        for (int i = tid; i < n; i += 256) {
            unsigned long long e = CAND[i];
            unsigned t12 = (unsigned)(e >> 52);
            bool take = t12 > B1 || (t12 == B1 && ((unsigned)(e >> 40) & 0xFFFu) >= B2);
            if (take) {
                int p = atomicAdd(&ctrl[2], 1);
                if (p < BUFN) BUF[p] = e;
            }
        }
        __syncthreads();
    } else {
        // ---- exact fallback: strided global scan of this class column ----
        unsigned cnt = 0;
        for (int a = tid; a < A_N; a += 256) {
            float x = pred[((size_t)b * A_N + a) * 84 + 4 + c];
            float s = 1.0f / (1.0f + expf(-x));
            if (s > 0.05f) { ++cnt; atomicAdd(&hist[fkey32(s) >> 20], 1u); }
        }
        for (int o = 16; o; o >>= 1) cnt += __shfl_down_sync(0xFFFFFFFFu, cnt, o);
        if ((tid & 31) == 0) atomicAdd((unsigned*)&ctrl[5], cnt);
        __syncthreads();
        const unsigned total = (unsigned)ctrl[5];
        if (total == 0u) {
            for (int p = tid; p < MDPC; p += 256) {
                g_cls_scores[task * MDPC + p] = -1.0f;
                g_cls_boxes [task * MDPC + p] = make_float4(0.f, 0.f, 0.f, 0.f);
            }
            return;
        }
        const unsigned target = total < (unsigned)KPRE ? total : (unsigned)KPRE;
        (void)suffix_total<16>(hist, csum, tid);
        crossing<16>(hist, csum, ctrl, target, tid);
        const unsigned B1 = (unsigned)ctrl[0];
        const unsigned C1 = (unsigned)ctrl[1];
        __syncthreads();
        for (int i = tid; i < NBIN; i += 256) hist[i] = 0;
        __syncthreads();
        for (int a = tid; a < A_N; a += 256) {
            float x = pred[((size_t)b * A_N + a) * 84 + 4 + c];
            float s = 1.0f / (1.0f + expf(-x));
            if (s > 0.05f) {
                unsigned key = fkey32(s);
                if ((key >> 20) == B1) atomicAdd(&hist[(key >> 8) & 0xFFFu], 1u);
            }
        }
        __syncthreads();
        (void)suffix_total<16>(hist, csum, tid);
        crossing<16>(hist, csum, ctrl, target - C1, tid);
        const unsigned B2 = (unsigned)ctrl[0];
        if (tid == 0) ctrl[2] = 0;
        __syncthreads();
        for (int a = tid; a < A_N; a += 256) {
            float x = pred[((size_t)b * A_N + a) * 84 + 4 + c];
            float s = 1.0f / (1.0f + expf(-x));
            if (s > 0.05f) {
                unsigned key = fkey32(s);
                unsigned t12 = key >> 20;
                bool take = t12 > B1 || (t12 == B1 && ((key >> 8) & 0xFFFu) >= B2);
                if (take) {
                    int p = atomicAdd(&ctrl[2], 1);
                    if (p < BUFN)
                        BUF[p] = ((unsigned long long)key << 32) | (unsigned)(~(unsigned)a);
                }
            }
        }
        __syncthreads();
    }

    int sel = ctrl[2]; if (sel > BUFN) sel = BUFN;
    const int W = (sel <= 512) ? 512 : 1024;
    for (int i = sel + tid; i < W; i += 256) BUF[i] = 0ull;
    __syncthreads();

    // ---- bitonic sort descending over W u64 ----
    for (int kk = 2; kk <= W; kk <<= 1) {
        for (int j = kk >> 1; j > 0; j >>= 1) {
            for (int i = tid; i < W; i += 256) {
                int ix = i ^ j;
                if (ix > i) {
                    unsigned long long x = BUF[i], y = BUF[ix];
                    bool sw = ((i & kk) == 0) ? (x < y) : (x > y);
                    if (sw) { BUF[i] = y; BUF[ix] = x; }
                }
            }
            __syncthreads();
        }
    }

    // ---- NMS on top-256 (aliases CAND region) ----
    float*    X1    = (float*)sm;
    float*    Y1    = (float*)(sm + 1024);
    float*    X2    = (float*)(sm + 2048);
    float*    Y2    = (float*)(sm + 3072);
    float*    AR    = (float*)(sm + 4096);
    float*    SC    = (float*)(sm + 5120);
    unsigned* MASKS = (unsigned*)(sm + 6144);
    unsigned* KEEPW = (unsigned*)(sm + 14336);
    unsigned* WPFX  = (unsigned*)(sm + 14400);

    {
        unsigned long long e = BUF[tid];
        unsigned key  = (unsigned)(e >> 32);
        unsigned aidx = ~(unsigned)(e & 0xFFFFFFFFull);
        float  s  = -1.0f;
        float4 bx = make_float4(0.f, 0.f, 0.f, 0.f);
        if (key) {
            const float4 bp = *(const float4*)(pred + ((size_t)b * A_N + aidx) * 84);
            const float4 an = ((const float4*)anchors)[aidx];
            float cx = bp.x * 0.1f * an.z + an.x;
            float cy = bp.y * 0.1f * an.w + an.y;
            float w  = expf(bp.z * 0.2f) * an.z;
            float h  = expf(bp.w * 0.2f) * an.w;
            bx = make_float4(cx - w * 0.5f, cy - h * 0.5f, cx + w * 0.5f, cy + h * 0.5f);
            s  = __uint_as_float(key & 0x7FFFFFFFu);
        }
        X1[tid] = bx.x; Y1[tid] = bx.y; X2[tid] = bx.z; Y2[tid] = bx.w;
        AR[tid] = (bx.z - bx.x) * (bx.w - bx.y);
        SC[tid] = s;
        unsigned bal = __ballot_sync(0xFFFFFFFFu, key != 0u);
        if ((tid & 31) == 0) KEEPW[tid >> 5] = bal;
    }
    __syncthreads();

    {
        float ax1 = X1[tid], ay1 = Y1[tid], ax2 = X2[tid], ay2 = Y2[tid], aa = AR[tid];
        for (int w = 0; w < 8; ++w) {
            unsigned m = 0;
            for (int l = 0; l < 32; ++l) {
                int j = w * 32 + l;
                if (j > tid) {
                    float iw = fmaxf(fminf(ax2, X2[j]) - fmaxf(ax1, X1[j]), 0.f);
                    float ih = fmaxf(fminf(ay2, Y2[j]) - fmaxf(ay1, Y1[j]), 0.f);
                    float inter = iw * ih;
                    float iou = inter / fmaxf(aa + AR[j] - inter, 1e-8f);
                    if (iou > 0.5f) m |= (1u << l);
                }
            }
            MASKS[tid * 8 + w] = m;
        }
    }
    __syncthreads();

    if (tid < 32) {
        unsigned kw = (tid < 8) ? KEEPW[tid] : 0u;
        for (int i = 0; i < 256; ++i) {
            unsigned word = __shfl_sync(0xFFFFFFFFu, kw, i >> 5);
            if ((word >> (i & 31)) & 1u) {
                if (tid < 8) kw &= ~MASKS[i * 8 + tid];
            }
        }
        if (tid < 8) KEEPW[tid] = kw;
    }
    __syncthreads();

    if (tid == 0) {
        unsigned run = 0;
        for (int w = 0; w < 8; ++w) { WPFX[w] = run; run += __popc(KEEPW[w]); }
        WPFX[8] = run;
    }
    __syncthreads();

    {
        unsigned w = tid >> 5, bpos = tid & 31;
        unsigned kwv = KEEPW[w];
        bool kept = (kwv >> bpos) & 1u;
        unsigned p = WPFX[w] + __popc(kwv & ((1u << bpos) - 1u));
        if (kept && p < MDPC) {
            g_cls_scores[task * MDPC + p] = SC[tid];
            g_cls_boxes [task * MDPC + p] = make_float4(X1[tid], Y1[tid], X2[tid], Y2[tid]);
        }
        int kc = (int)WPFX[8];
        for (int q = kc + tid; q < MDPC; q += 256) {
            g_cls_scores[task * MDPC + q] = -1.0f;
            g_cls_boxes [task * MDPC + q] = make_float4(0.f, 0.f, 0.f, 0.f);
        }
    }
}

// =====================================================================
// Kernel 3: per image top-100 of 8000 via histogram select + 256-sort
// =====================================================================
__global__ void __launch_bounds__(256) k_final(float* __restrict__ out) {
    __shared__ unsigned hist[NBIN];
    __shared__ unsigned long long BUF[256];
    __shared__ unsigned csum[257];
    __shared__ int ctrl[8];
    __shared__ int vc;

    const int tid = threadIdx.x;
    const int b   = blockIdx.x;
    const float* sc = g_cls_scores + b * NCLS * MDPC;

    for (int i = tid; i < NBIN; i += 256) hist[i] = 0;
    if (tid < 8) ctrl[tid] = 0;
    __syncthreads();

    unsigned cnt = 0;
    for (int i = tid; i < NCLS * MDPC; i += 256) {
        float s = sc[i];
        if (s > 0.0f) { ++cnt; atomicAdd(&hist[fkey32(s) >> 20], 1u); }
    }
    for (int o = 16; o; o >>= 1) cnt += __shfl_down_sync(0xFFFFFFFFu, cnt, o);
    if ((tid & 31) == 0) atomicAdd((unsigned*)&ctrl[5], cnt);
    __syncthreads();
    const unsigned npos = (unsigned)ctrl[5];

    if (npos >= (unsigned)MAXD) {
        (void)suffix_total<16>(hist, csum, tid);
        crossing<16>(hist, csum, ctrl, MAXD, tid);
        const unsigned B1 = (unsigned)ctrl[0];
        const unsigned C1 = (unsigned)ctrl[1];
        __syncthreads();
        for (int i = tid; i < NBIN; i += 256) hist[i] = 0;
        __syncthreads();
        for (int i = tid; i < NCLS * MDPC; i += 256) {
            float s = sc[i];
            if (s > 0.0f) {
                unsigned key = fkey32(s);
                if ((key >> 20) == B1) atomicAdd(&hist[(key >> 8) & 0xFFFu], 1u);
            }
        }
        __syncthreads();
        (void)suffix_total<16>(hist, csum, tid);
        crossing<16>(hist, csum, ctrl, MAXD - C1, tid);
        const unsigned B2 = (unsigned)ctrl[0];
        if (tid == 0) ctrl[2] = 0;
        __syncthreads();
        for (int i = tid; i < NCLS * MDPC; i += 256) {
            float s = sc[i];
            if (s > 0.0f) {
                unsigned key = fkey32(s);
                unsigned t12 = key >> 20;
                bool take = t12 > B1 || (t12 == B1 && ((key >> 8) & 0xFFFu) >= B2);
                if (take) {
                    int p = atomicAdd(&ctrl[2], 1);
                    if (p < 256)
                        BUF[p] = ((unsigned long long)key << 32) | (unsigned)(~(unsigned)i);
                }
            }
        }
        __syncthreads();
    } else {
        if (tid == 0) ctrl[2] = 0;
        __syncthreads();
        for (int i = tid; i < NCLS * MDPC; i += 256) {
            float s = sc[i];
            if (s > 0.0f) {
                int p = atomicAdd(&ctrl[2], 1);
                if (p < 256)
                    BUF[p] = ((unsigned long long)fkey32(s) << 32) | (unsigned)(~(unsigned)i);
            }
        }
        __syncthreads();
    }

    int sel = ctrl[2]; if (sel > 256) sel = 256;
    if (tid >= sel) BUF[tid] = 0ull;
    __syncthreads();

    // bitonic sort 256 descending
    for (int kk = 2; kk <= 256; kk <<= 1) {
        for (int j = kk >> 1; j > 0; j >>= 1) {
            int ix = tid ^ j;
            if (ix > tid) {
                unsigned long long x = BUF[tid], y = BUF[ix];
                bool sw = ((tid & kk) == 0) ? (x < y) : (x > y);
                if (sw) { BUF[tid] = y; BUF[ix] = x; }
            }
            __syncthreads();
        }
    }

    if (tid == 0) vc = 0;
    __syncthreads();

    if (tid < MAXD) {
        unsigned long long e = BUF[tid];
        unsigned key  = (unsigned)(e >> 32);
        unsigned flat = ~(unsigned)(e & 0xFFFFFFFFull);
        bool valid = (key != 0u);
        float4 bx = make_float4(0.f, 0.f, 0.f, 0.f);
        float cls = 0.0f, so = 0.0f;
        if (valid) {
            float s = __uint_as_float((key & 0x80000000u) ? (key & 0x7FFFFFFFu) : ~key);
            bx  = g_cls_boxes[b * NCLS * MDPC + flat];
            cls = (float)(flat / MDPC);
            so  = s;
            atomicAdd(&vc, 1);
        }
        out[b * 400 + tid * 4 + 0] = bx.x;
        out[b * 400 + tid * 4 + 1] = bx.y;
        out[b * 400 + tid * 4 + 2] = bx.z;
        out[b * 400 + tid * 4 + 3] = bx.w;
        out[NB * MAXD * 4 + b * MAXD + tid]             = so;
        out[NB * MAXD * 4 + NB * MAXD + b * MAXD + tid] = cls;
    }
    __syncthreads();
    if (tid == 0) out[NB * MAXD * 6 + b] = (float)vc;
}

// =====================================================================
extern "C" void kernel_launch(void* const* d_in, const int* in_sizes, int n_in,
                              void* d_out, int out_size) {
    (void)in_sizes; (void)n_in; (void)out_size;
    const float* pred    = (const float*)d_in[1];
    const float* anchors = (const float*)d_in[2];
    float* out = (float*)d_out;

    k_zero<<<3, 256>>>();
    k_decode<<<NB * 600, 256>>>(pred);

    cudaFuncSetAttribute(k_select, cudaFuncAttributeMaxDynamicSharedMemorySize, 50216);
    k_select<<<NTASK, 256, 50216>>>(pred, anchors);

    k_final<<<NB, 256>>>(out);
}